// round 9
// baseline (speedup 1.0000x reference)
#include <cuda_runtime.h>
#include <cuda_fp16.h>
#include <math.h>
#include <stdint.h>

// Problem constants
#define B_   1024
#define S_   128
#define D_   256
#define H_   2048
#define O_   10
#define V_   10

// Step tiling
#define BM   128
#define BN   128
#define KT   64            // fp16 per K-tile => 128B of payload per row
#define NKT  (H_ / KT)     // 32
#define NB   4             // 4-stage DMA pipeline (32 % 4 == 0 -> clean parity)
#define ROWB 144           // padded smem row stride: 144/16=9 => conflict-free LDSM
#define OPBYTES (128 * ROWB)          // 18432 per operand tile
#define STGBYTES (2 * OPBYTES)        // 36864 per stage (A + B)
#define TXBYTES (2 * 128 * 128)       // 32768 actual DMA bytes per stage

// Scratch
__device__ __half g_h0[B_ * H_];
__device__ __half g_h1[B_ * H_];
__device__ float  g_T [V_ * H_];    // W_hx @ embed[v] + b_hx   (for h0)
__device__ float  g_T2[V_ * H_];    // g_T + b_hh               (for steps)
__device__ __half g_Wh[H_ * H_];    // fp16 W_hh, row-major [h][k]
__device__ unsigned g_bar;          // grid barrier (cumulative)

// ---------------------------------------------------------------------------
// helpers
// ---------------------------------------------------------------------------
__device__ __forceinline__ uint32_t smem_u32(const void* p) {
    uint32_t a;
    asm("{ .reg .u64 t; cvta.to.shared.u64 t, %1; cvt.u32.u64 %0, t; }" : "=r"(a) : "l"(p));
    return a;
}

#define MBAR_INIT(a, c) \
    asm volatile("mbarrier.init.shared.b64 [%0], %1;" :: "r"(a), "r"(c) : "memory")
#define MBAR_EXPECT(a, bytes) \
    asm volatile("mbarrier.arrive.expect_tx.shared.b64 _, [%0], %1;" \
                 :: "r"(a), "r"(bytes) : "memory")
#define MBAR_WAIT(a, ph) do {                                                   \
    uint32_t _m = (a), _p = (ph), _d;                                           \
    asm volatile("{\n\t.reg .pred p;\n\t"                                       \
        "mbarrier.try_wait.parity.acquire.cta.shared::cta.b64 p, [%1], %2;\n\t" \
        "selp.b32 %0, 1, 0, p;\n\t}" : "=r"(_d) : "r"(_m), "r"(_p) : "memory"); \
    if (!_d) {                                                                  \
        asm volatile("{\n\t.reg .pred P1;\n\t"                                  \
        "WL_%=:\n\t"                                                            \
        "mbarrier.try_wait.parity.acquire.cta.shared::cta.b64 P1, [%0], %1, 0x989680;\n\t" \
        "@P1 bra.uni WD_%=;\n\t"                                                \
        "bra.uni WL_%=;\n\t"                                                    \
        "WD_%=:\n\t}" :: "r"(_m), "r"(_p) : "memory");                          \
    }                                                                           \
} while (0)

// one 128-byte bulk DMA row copy, completion on mbarrier
#define BULK128(dst, src, mb)                                                   \
    asm volatile("cp.async.bulk.shared::cta.global.mbarrier::complete_tx::bytes " \
                 "[%0], [%1], 128, [%2];"                                       \
                 :: "r"(dst), "l"(src), "r"(mb) : "memory")

#define LDSM4(R, A)                                                        \
    asm volatile("ldmatrix.sync.aligned.m8n8.x4.shared.b16 "               \
                 "{%0,%1,%2,%3}, [%4];"                                    \
                 : "=r"((R)[0]), "=r"((R)[1]), "=r"((R)[2]), "=r"((R)[3])  \
                 : "r"(A))

__device__ __forceinline__ void mma16816(float* d, const uint32_t* a,
                                         uint32_t b0, uint32_t b1) {
    asm volatile(
        "mma.sync.aligned.m16n8k16.row.col.f32.f16.f16.f32 "
        "{%0,%1,%2,%3}, {%4,%5,%6,%7}, {%8,%9}, {%0,%1,%2,%3};\n"
        : "+f"(d[0]), "+f"(d[1]), "+f"(d[2]), "+f"(d[3])
        : "r"(a[0]), "r"(a[1]), "r"(a[2]), "r"(a[3]), "r"(b0), "r"(b1));
}

// tanh(x) = 1 - 2/(e^{2x}+1) via MUFU ex2 + rcp; rel err ~1e-6.
__device__ __forceinline__ float fast_tanh(float x) {
    float e;
    asm("ex2.approx.f32 %0, %1;" : "=f"(e) : "f"(x * 2.8853900817779268f));
    float r;
    asm("rcp.approx.f32 %0, %1;" : "=f"(r) : "f"(e + 1.0f));
    return fmaf(-2.0f, r, 1.0f);
}

// ---------------------------------------------------------------------------
// Setup kernels
// ---------------------------------------------------------------------------
__global__ void precompute_T_kernel(const float* __restrict__ embed,
                                    const float* __restrict__ W_hx,
                                    const float* __restrict__ b_hx) {
    int h = blockIdx.x * blockDim.x + threadIdx.x;
    int v = blockIdx.y;
    if (h >= H_) return;
    const float4* wr = reinterpret_cast<const float4*>(W_hx + (size_t)h * D_);
    const float4* er = reinterpret_cast<const float4*>(embed + (size_t)v * D_);
    float s = 0.f;
#pragma unroll 8
    for (int i = 0; i < D_ / 4; i++) {
        float4 w = wr[i];
        float4 e = er[i];
        s += w.x * e.x + w.y * e.y + w.z * e.z + w.w * e.w;
    }
    g_T[v * H_ + h] = s + b_hx[h];
}

__global__ void make_T2_kernel(const float* __restrict__ b_hh) {
    int i = blockIdx.x * blockDim.x + threadIdx.x;
    g_T2[i] = g_T[i] + b_hh[i & (H_ - 1)];
}

__global__ void cvt_W_kernel(const float* __restrict__ W) {
    int i = blockIdx.x * blockDim.x + threadIdx.x;
    g_Wh[i] = __float2half(W[i]);
}

__global__ void init_h_kernel(const int* __restrict__ x) {
    int idx = blockIdx.x * blockDim.x + threadIdx.x;
    if (idx == 0) g_bar = 0u;
    int b = idx >> 11;
    int h = idx & (H_ - 1);
    int tok = x[b * S_];
    g_h0[idx] = __float2half(fast_tanh(g_T[tok * H_ + h]));
}

// ---------------------------------------------------------------------------
// Persistent recurrence kernel: 127 steps, grid (16,8)=128 CTAs (one wave),
// 256 threads. Per step: 128x128x2048 fp16 HMMA GEMM with bulk-DMA operand
// staging (mbarrier complete_tx), fused epilogue, grid barrier. Next step's
// W half-tiles are DMA'd across the barrier (W doesn't depend on h).
// ---------------------------------------------------------------------------
__global__ __launch_bounds__(256, 1)
void rnn_persist(const int* __restrict__ x) {
    extern __shared__ char dsm[];
    const uint32_t sraw  = smem_u32(dsm);
    const uint32_t mbarB = (sraw + 127) & ~127u;   // 4 mbarriers
    const uint32_t smT   = mbarB + 128;            // 4 stages x (A|B)

    const int tid  = threadIdx.x;
    const int warp = tid >> 5;
    const int lane = tid & 31;
    const int bm0  = blockIdx.y * BM;
    const int bn0  = blockIdx.x * BN;
    const int wm   = warp >> 2;
    const int wn   = warp & 3;

    // mbarrier init (count=1: single expect_tx arrival per phase)
    if (tid == 0) {
#pragma unroll
        for (int s = 0; s < NB; s++) MBAR_INIT(mbarB + 8 * s, 1);
    }
    __syncthreads();

    // ---- loader mapping: thread tid<128 copies A row tid; else B row tid-128
    const int lrow = tid & 127;
    const uint32_t dstOff = (uint32_t)lrow * ROWB;
    const size_t  aoff = (size_t)(bm0 + lrow) * (H_ * 2);          // A row byte offset
    const char*   srcB = (const char*)g_Wh + (size_t)(bn0 + lrow) * (H_ * 2);

#define STAGE_A(s) (smT + (uint32_t)(s) * STGBYTES)
#define STAGE_B(s) (smT + (uint32_t)(s) * STGBYTES + OPBYTES)

#define ISSUE_FULL(NT, ASRC)                                               \
    do {                                                                   \
        uint32_t _st = (NT) & 3;                                           \
        uint32_t _mb = mbarB + _st * 8;                                    \
        if (tid == 0) MBAR_EXPECT(_mb, (uint32_t)TXBYTES);                 \
        uint32_t _kb = (uint32_t)(NT) * 128;                               \
        if (tid < 128) BULK128(STAGE_A(_st) + dstOff, (ASRC) + aoff + _kb, _mb); \
        else           BULK128(STAGE_B(_st) + dstOff, srcB + _kb, _mb);    \
    } while (0)

#define ISSUE_B_ONLY(KTI)                                                  \
    do {                                                                   \
        uint32_t _st = (KTI) & 3;                                          \
        uint32_t _mb = mbarB + _st * 8;                                    \
        if (tid == 0) MBAR_EXPECT(_mb, (uint32_t)TXBYTES);                 \
        if (tid >= 128) BULK128(STAGE_B(_st) + dstOff,                     \
                                srcB + (uint32_t)(KTI) * 128, _mb);        \
    } while (0)

#define ISSUE_A_ONLY(KTI, ASRC)                                            \
    do {                                                                   \
        uint32_t _st = (KTI) & 3;                                          \
        uint32_t _mb = mbarB + _st * 8;                                    \
        if (tid < 128) BULK128(STAGE_A(_st) + dstOff,                      \
                               (ASRC) + aoff + (uint32_t)(KTI) * 128, _mb);\
    } while (0)

    // ---- ldmatrix lane addresses (row stride 144B, no swizzle needed) ----
    uint32_t rA144[4];
    const uint32_t pA = lane >> 4;
#pragma unroll
    for (int f = 0; f < 4; f++) {
        uint32_t r = wm * 64 + f * 16 + (lane & 7) + ((lane >> 3) & 1) * 8;
        rA144[f] = r * ROWB;
    }
    uint32_t rB144[2];
    const uint32_t pB = (lane >> 3) & 1;
#pragma unroll
    for (int q = 0; q < 2; q++) {
        uint32_t r = wn * 32 + q * 16 + (lane & 7) + ((lane >> 4) & 1) * 8;
        rB144[q] = r * ROWB;
    }

#define LOAD_FRAGS(DA, DB, SA, SB, S)                                      \
    do {                                                                   \
        _Pragma("unroll")                                                  \
        for (int _f = 0; _f < 4; _f++) {                                   \
            uint32_t _ad = (SA) + rA144[_f] + ((2u * (S) + pA) << 4);      \
            LDSM4((DA)[_f], _ad);                                          \
        }                                                                  \
        _Pragma("unroll")                                                  \
        for (int _q = 0; _q < 2; _q++) {                                   \
            uint32_t _ad = (SB) + rB144[_q] + ((2u * (S) + pB) << 4);      \
            LDSM4((DB)[_q], _ad);                                          \
        }                                                                  \
    } while (0)

    // epilogue constants
    const int erlo = bm0 + wm * 64 + (lane >> 2);    // + f*16
    const int ecol = bn0 + wn * 32 + (lane & 3) * 2; // + n*8

    // ---- prologue for step 1: stages 0..2 (A from g_h0) ----
    const char* As = (const char*)g_h0;
    ISSUE_FULL(0, As);
    ISSUE_FULL(1, As);
    ISSUE_FULL(2, As);

    // ---- time loop ----
#pragma unroll 1
    for (int t = 1; t < S_; ++t) {
        const int par = (t - 1) & 1;
        __half* __restrict__ Cg = par ? g_h0 : g_h1;

        float acc[4][4][4];
#pragma unroll
        for (int f = 0; f < 4; f++)
#pragma unroll
            for (int n = 0; n < 4; n++)
#pragma unroll
                for (int k = 0; k < 4; k++) acc[f][n][k] = 0.f;

        uint32_t afr[2][4][4], bfr[2][2][4];

#pragma unroll 1
        for (int it = 0; it < NKT; ++it) {
            MBAR_WAIT(mbarB + (it & 3) * 8, (it >> 2) & 1);
            __syncthreads();   // all warps past old data before stage reuse

            const int nt = it + 3;
            if (nt < NKT) {
                ISSUE_FULL(nt, As);
            } else if (t < S_ - 1) {
                ISSUE_B_ONLY(nt - NKT);   // next step's W half across barrier
            }

            const uint32_t sa = STAGE_A(it & 3);
            const uint32_t sb = STAGE_B(it & 3);

            LOAD_FRAGS(afr[0], bfr[0], sa, sb, 0);
#pragma unroll
            for (int s = 0; s < 4; s++) {
                const int cur = s & 1;
                if (s < 3) LOAD_FRAGS(afr[cur ^ 1], bfr[cur ^ 1], sa, sb, s + 1);
#pragma unroll
                for (int f = 0; f < 4; f++)
#pragma unroll
                    for (int n = 0; n < 4; n++)
                        mma16816(acc[f][n], afr[cur][f],
                                 bfr[cur][n >> 1][(n & 1) * 2],
                                 bfr[cur][n >> 1][(n & 1) * 2 + 1]);
            }
        }

        // ---- fused epilogue: + T2[x[b,t]], tanh, fp16 store ----
#pragma unroll
        for (int f = 0; f < 4; f++) {
            int rlo = erlo + f * 16;
            int rhi = rlo + 8;
            const float* Tlo = g_T2 + x[rlo * S_ + t] * H_;
            const float* Thi = g_T2 + x[rhi * S_ + t] * H_;
#pragma unroll
            for (int n = 0; n < 4; n++) {
                int col = ecol + n * 8;
                float v0 = fast_tanh(acc[f][n][0] + Tlo[col]);
                float v1 = fast_tanh(acc[f][n][1] + Tlo[col + 1]);
                *(__half2*)(Cg + (size_t)rlo * H_ + col) = __floats2half2_rn(v0, v1);
                v0 = fast_tanh(acc[f][n][2] + Thi[col]);
                v1 = fast_tanh(acc[f][n][3] + Thi[col + 1]);
                *(__half2*)(Cg + (size_t)rhi * H_ + col) = __floats2half2_rn(v0, v1);
            }
        }

        // ---- grid barrier, then A halves for next step's stages 0..2 ----
        if (t < S_ - 1) {
            __syncthreads();
            if (tid == 0) {
                asm volatile("red.release.gpu.add.u32 [%0], %1;"
                             :: "l"(&g_bar), "r"(1u) : "memory");
                unsigned tgt = 128u * (unsigned)t;
                unsigned v;
                do {
                    asm volatile("ld.acquire.gpu.u32 %0, [%1];"
                                 : "=r"(v) : "l"(&g_bar) : "memory");
                } while (v < tgt);
            }
            __syncthreads();

            As = (const char*)Cg;      // next step reads what we just wrote
            ISSUE_A_ONLY(0, As);
            ISSUE_A_ONLY(1, As);
            ISSUE_A_ONLY(2, As);
        }
    }
#undef STAGE_A
#undef STAGE_B
#undef ISSUE_FULL
#undef ISSUE_B_ONLY
#undef ISSUE_A_ONLY
#undef LOAD_FRAGS
}

// ---------------------------------------------------------------------------
// Output: o = hT @ W_oh^T + b_oh ; softmax over O=10 (h fp16, in g_h1)
// ---------------------------------------------------------------------------
__global__ __launch_bounds__(256)
void output_softmax_kernel(const float* __restrict__ W_oh,
                           const float* __restrict__ b_oh,
                           float* __restrict__ out) {
    const int b = blockIdx.x;
    const int tid = threadIdx.x;
    const __half* hrow = g_h1 + (size_t)b * H_;

    float acc[O_];
#pragma unroll
    for (int j = 0; j < O_; j++) acc[j] = 0.f;

    for (int k = tid; k < H_; k += 256) {
        float hv = __half2float(hrow[k]);
#pragma unroll
        for (int j = 0; j < O_; j++) acc[j] += hv * W_oh[j * H_ + k];
    }
#pragma unroll
    for (int off = 16; off > 0; off >>= 1)
#pragma unroll
        for (int j = 0; j < O_; j++)
            acc[j] += __shfl_down_sync(0xffffffffu, acc[j], off);

    __shared__ float part[8][O_];
    if ((tid & 31) == 0) {
#pragma unroll
        for (int j = 0; j < O_; j++) part[tid >> 5][j] = acc[j];
    }
    __syncthreads();

    if (tid == 0) {
        float o[O_];
#pragma unroll
        for (int j = 0; j < O_; j++) {
            float s = b_oh[j];
#pragma unroll
            for (int w = 0; w < 8; w++) s += part[w][j];
            o[j] = s;
        }
        float m = o[0];
#pragma unroll
        for (int j = 1; j < O_; j++) m = fmaxf(m, o[j]);
        float s = 0.f;
#pragma unroll
        for (int j = 0; j < O_; j++) { o[j] = expf(o[j] - m); s += o[j]; }
        float inv = 1.f / s;
#pragma unroll
        for (int j = 0; j < O_; j++) out[b * O_ + j] = o[j] * inv;
    }
}

// ---------------------------------------------------------------------------
// Launch (graph-capturable; no allocs/syncs).
// Inputs: x, embed, W_hx, b_hx, W_hh, b_hh, W_oh, b_oh
// ---------------------------------------------------------------------------
#define STEP_SMEM (256 + NB * STGBYTES)

extern "C" void kernel_launch(void* const* d_in, const int* in_sizes, int n_in,
                              void* d_out, int out_size) {
    const int*   x     = (const int*)  d_in[0];
    const float* embed = (const float*)d_in[1];
    const float* W_hx  = (const float*)d_in[2];
    const float* b_hx  = (const float*)d_in[3];
    const float* W_hh  = (const float*)d_in[4];
    const float* b_hh  = (const float*)d_in[5];
    const float* W_oh  = (const float*)d_in[6];
    const float* b_oh  = (const float*)d_in[7];
    float* out = (float*)d_out;

    cudaFuncSetAttribute(rnn_persist,
                         cudaFuncAttributeMaxDynamicSharedMemorySize, STEP_SMEM);

    precompute_T_kernel<<<dim3(H_ / 256, V_), 256>>>(embed, W_hx, b_hx);
    make_T2_kernel<<<(V_ * H_) / 256, 256>>>(b_hh);
    cvt_W_kernel<<<(H_ * H_) / 256, 256>>>(W_hh);
    init_h_kernel<<<(B_ * H_) / 256, 256>>>(x);

    rnn_persist<<<dim3(H_ / BN, B_ / BM), 256, STEP_SMEM>>>(x);   // (16,8)=128 CTAs

    output_softmax_kernel<<<B_, 256>>>(W_oh, b_oh, out);
}

// round 11
// speedup vs baseline: 1.6702x; 1.6702x over previous
#include <cuda_runtime.h>
#include <cuda_fp16.h>
#include <math.h>
#include <stdint.h>

// Problem constants
#define B_   1024
#define S_   128
#define D_   256
#define H_   2048
#define O_   10
#define V_   10

// Step tiling
#define BM   128
#define BN   128
#define KT   64            // fp16 per K-tile => 128B/row (SW128 atom)
#define NKT  (H_ / KT)     // 32
#define NB   4             // 4-stage cp.async pipeline (A tiles only)
#define TILE_BYTES 16384   // 128 rows x 128B

// Scratch
__device__ __half g_h0[B_ * H_];
__device__ __half g_h1[B_ * H_];
__device__ float  g_T [V_ * H_];    // W_hx @ embed[v] + b_hx   (for h0)
__device__ float  g_T2[V_ * H_];    // g_T + b_hh               (for steps)
__device__ __half g_Wpk[H_ * H_];   // W_hh packed in mma B-fragment order
__device__ unsigned g_bar;          // grid barrier (cumulative)

// ---------------------------------------------------------------------------
// helpers
// ---------------------------------------------------------------------------
__device__ __forceinline__ uint32_t smem_u32(const void* p) {
    uint32_t a;
    asm("{ .reg .u64 t; cvta.to.shared.u64 t, %1; cvt.u32.u64 %0, t; }" : "=r"(a) : "l"(p));
    return a;
}
#define SWZ128(o) ((o) ^ (((o) >> 3) & 0x70))

#define CP_ASYNC16(dst, src) \
    asm volatile("cp.async.cg.shared.global [%0], [%1], 16;\n" :: "r"(dst), "l"(src))
#define CP_COMMIT() asm volatile("cp.async.commit_group;\n" ::: "memory")
#define CP_WAIT(n)  asm volatile("cp.async.wait_group %0;\n" :: "n"(n) : "memory")

#define LDSM4(R, A)                                                        \
    asm volatile("ldmatrix.sync.aligned.m8n8.x4.shared.b16 "               \
                 "{%0,%1,%2,%3}, [%4];"                                    \
                 : "=r"((R)[0]), "=r"((R)[1]), "=r"((R)[2]), "=r"((R)[3])  \
                 : "r"(A))

__device__ __forceinline__ void mma16816(float* d, const uint32_t* a,
                                         uint32_t b0, uint32_t b1) {
    asm volatile(
        "mma.sync.aligned.m16n8k16.row.col.f32.f16.f16.f32 "
        "{%0,%1,%2,%3}, {%4,%5,%6,%7}, {%8,%9}, {%0,%1,%2,%3};\n"
        : "+f"(d[0]), "+f"(d[1]), "+f"(d[2]), "+f"(d[3])
        : "r"(a[0]), "r"(a[1]), "r"(a[2]), "r"(a[3]), "r"(b0), "r"(b1));
}

// tanh(x) = 1 - 2/(e^{2x}+1) via MUFU ex2 + rcp; rel err ~1e-6.
__device__ __forceinline__ float fast_tanh(float x) {
    float e;
    asm("ex2.approx.f32 %0, %1;" : "=f"(e) : "f"(x * 2.8853900817779268f));
    float r;
    asm("rcp.approx.f32 %0, %1;" : "=f"(r) : "f"(e + 1.0f));
    return fmaf(-2.0f, r, 1.0f);
}

// ---------------------------------------------------------------------------
// Setup kernels
// ---------------------------------------------------------------------------
__global__ void precompute_T_kernel(const float* __restrict__ embed,
                                    const float* __restrict__ W_hx,
                                    const float* __restrict__ b_hx) {
    int h = blockIdx.x * blockDim.x + threadIdx.x;
    int v = blockIdx.y;
    if (h >= H_) return;
    const float4* wr = reinterpret_cast<const float4*>(W_hx + (size_t)h * D_);
    const float4* er = reinterpret_cast<const float4*>(embed + (size_t)v * D_);
    float s = 0.f;
#pragma unroll 8
    for (int i = 0; i < D_ / 4; i++) {
        float4 w = wr[i];
        float4 e = er[i];
        s += w.x * e.x + w.y * e.y + w.z * e.z + w.w * e.w;
    }
    g_T[v * H_ + h] = s + b_hx[h];
}

__global__ void make_T2_kernel(const float* __restrict__ b_hh) {
    int i = blockIdx.x * blockDim.x + threadIdx.x;
    g_T2[i] = g_T[i] + b_hh[i & (H_ - 1)];
}

// Pack W_hh into mma.m16n8k16 B-fragment order:
//   id bits: [0:4)=o (16 halfs/lane), [4:9)=lane, [9:11)=wn, [11:18)=ks, [18:22)=bn_tile
//   lane's 16 halfs = 4 n8-fragments q=0..3, each {b0.lo,b0.hi,b1.lo,b1.hi}:
//     n = bt*128 + wn*32 + q*8 + (lane>>2)
//     k = ks*16 + (lane&3)*2 + (j&1) + (j>>1)*8
__global__ void pack_W_kernel(const float* __restrict__ W) {
    int id = blockIdx.x * blockDim.x + threadIdx.x;
    int o    = id & 15;
    int lane = (id >> 4) & 31;
    int wn   = (id >> 9) & 3;
    int ks   = (id >> 11) & 127;
    int bt   = id >> 18;
    int q = o >> 2, j = o & 3;
    int n = bt * 128 + wn * 32 + q * 8 + (lane >> 2);
    int k = ks * 16 + (lane & 3) * 2 + (j & 1) + (j >> 1) * 8;
    g_Wpk[id] = __float2half(W[(size_t)n * H_ + k]);
}

__global__ void init_h_kernel(const int* __restrict__ x) {
    int idx = blockIdx.x * blockDim.x + threadIdx.x;
    if (idx == 0) g_bar = 0u;
    int b = idx >> 11;
    int h = idx & (H_ - 1);
    int tok = x[b * S_];
    g_h0[idx] = __float2half(fast_tanh(g_T[tok * H_ + h]));
}

// ---------------------------------------------------------------------------
// Persistent recurrence kernel. Grid (16,8)=128 CTAs (one wave), 256 threads.
// Per step: 128x128x2048 fp16 HMMA. A staged via cp.async (4 stages, SW128);
// W read directly into registers from the packed fragment table (LDG.128 x2
// per lane per k16-step, double-buffered, prefetch wraps across steps).
// ---------------------------------------------------------------------------
__global__ __launch_bounds__(256, 1)
void rnn_persist(const int* __restrict__ x) {
    extern __shared__ char dsm[];
    const uint32_t sraw = smem_u32(dsm);
    const uint32_t smA  = (sraw + 1023) & ~1023u;

    const int tid  = threadIdx.x;
    const int warp = tid >> 5;
    const int lane = tid & 31;
    const int bm0  = blockIdx.y * BM;
    const int wm   = warp >> 2;
    const int wn   = warp & 3;

    // ---- A loader: 4 x cp.async(16B)/thread: rows r0+32j, chunk ch8 ----
    const int ch8 = tid & 7;
    const int r0  = tid >> 3;
    size_t aoff[4];
    uint32_t offR[4];
#pragma unroll
    for (int j = 0; j < 4; j++) {
        int row = r0 + 32 * j;
        aoff[j] = (size_t)(bm0 + row) * (H_ * 2) + ch8 * 16;
        offR[j] = SWZ128((uint32_t)(row * 128 + ch8 * 16));
    }

#define LOAD_A(ABASE, TT, BUF)                                        \
    do {                                                              \
        size_t _kb = (size_t)(TT) * 128;                              \
        uint32_t _da = smA + (BUF) * TILE_BYTES;                      \
        CP_ASYNC16(_da + offR[0], (ABASE) + aoff[0] + _kb);           \
        CP_ASYNC16(_da + offR[1], (ABASE) + aoff[1] + _kb);           \
        CP_ASYNC16(_da + offR[2], (ABASE) + aoff[2] + _kb);           \
        CP_ASYNC16(_da + offR[3], (ABASE) + aoff[3] + _kb);           \
        CP_COMMIT();                                                  \
    } while (0)

    // ---- W fragment pointer: packed table, per (bn_tile, wn, lane) ----
    // layout: bn_tile stride 512KB, ks stride 4096B, wn stride 1024B, lane 32B
    const uint4* __restrict__ wbase = (const uint4*)(
        (const char*)g_Wpk + ((size_t)blockIdx.x << 19)
        + (uint32_t)wn * 1024u + (uint32_t)lane * 32u);

    // ---- ldmatrix A lane addresses (SW128) ----
    uint32_t rA128[4], rA7[4];
    const uint32_t pA = lane >> 4;
#pragma unroll
    for (int f = 0; f < 4; f++) {
        uint32_t r = wm * 64 + f * 16 + (lane & 7) + ((lane >> 3) & 1) * 8;
        rA128[f] = r * 128;
        rA7[f]   = r & 7;
    }

#define LOAD_AFRAGS(DA, SA, S)                                             \
    do {                                                                   \
        _Pragma("unroll")                                                  \
        for (int _f = 0; _f < 4; _f++) {                                   \
            uint32_t _ad = (SA) + rA128[_f] + ((((2u*(S)) + pA) ^ rA7[_f]) << 4);\
            LDSM4((DA)[_f], _ad);                                          \
        }                                                                  \
    } while (0)

    // epilogue constants
    const int erlo = bm0 + wm * 64 + (lane >> 2);              // + f*16
    const int ecol = blockIdx.x * BN + wn * 32 + (lane & 3) * 2; // + n*8

    // ---- W register double buffer; preload ks=0 ----
    uint4 wlo[2], whi[2];
    wlo[0] = wbase[0];
    whi[0] = wbase[1];

    // ---- prologue for step 1 ----
    const char* As = (const char*)g_h0;
    LOAD_A(As, 0, 0);
    LOAD_A(As, 1, 1);
    LOAD_A(As, 2, 2);

    // ---- time loop ----
#pragma unroll 1
    for (int t = 1; t < S_; ++t) {
        const int par = (t - 1) & 1;
        __half* __restrict__ Cg = par ? g_h0 : g_h1;

        float acc[4][4][4];
#pragma unroll
        for (int f = 0; f < 4; f++)
#pragma unroll
            for (int n = 0; n < 4; n++)
#pragma unroll
                for (int k = 0; k < 4; k++) acc[f][n][k] = 0.f;

        uint32_t afr[2][4][4];

#pragma unroll 1
        for (int it = 0; it < NKT; ++it) {
            if (it < NKT - 2)       { CP_WAIT(2); }
            else if (it == NKT - 2) { CP_WAIT(1); }
            else                    { CP_WAIT(0); }
            __syncthreads();
            if (it + 3 < NKT) LOAD_A(As, it + 3, (it + 3) & 3);

            const uint32_t sa = smA + (it & 3) * TILE_BYTES;
            LOAD_AFRAGS(afr[0], sa, 0);

#pragma unroll
            for (int s = 0; s < 4; s++) {
                const int cur = s & 1;                  // == ks&1 (it*4 even)
                // prefetch W for next k16-step (wraps 127 -> 0 across steps)
                const uint32_t ksn = ((uint32_t)(it * 4 + s) + 1u) & 127u;
                wlo[cur ^ 1] = wbase[ksn * 256u];
                whi[cur ^ 1] = wbase[ksn * 256u + 1u];

                if (s < 3) LOAD_AFRAGS(afr[cur ^ 1], sa, s + 1);

                const uint32_t b0[4] = { wlo[cur].x, wlo[cur].z, whi[cur].x, whi[cur].z };
                const uint32_t b1[4] = { wlo[cur].y, wlo[cur].w, whi[cur].y, whi[cur].w };
#pragma unroll
                for (int f = 0; f < 4; f++)
#pragma unroll
                    for (int n = 0; n < 4; n++)
                        mma16816(acc[f][n], afr[cur][f], b0[n], b1[n]);
            }
        }

        // ---- fused epilogue: + T2[x[b,t]], tanh, fp16 store ----
#pragma unroll
        for (int f = 0; f < 4; f++) {
            int rlo = erlo + f * 16;
            int rhi = rlo + 8;
            const float* Tlo = g_T2 + x[rlo * S_ + t] * H_;
            const float* Thi = g_T2 + x[rhi * S_ + t] * H_;
#pragma unroll
            for (int n = 0; n < 4; n++) {
                int col = ecol + n * 8;
                float v0 = fast_tanh(acc[f][n][0] + Tlo[col]);
                float v1 = fast_tanh(acc[f][n][1] + Tlo[col + 1]);
                *(__half2*)(Cg + (size_t)rlo * H_ + col) = __floats2half2_rn(v0, v1);
                v0 = fast_tanh(acc[f][n][2] + Thi[col]);
                v1 = fast_tanh(acc[f][n][3] + Thi[col + 1]);
                *(__half2*)(Cg + (size_t)rhi * H_ + col) = __floats2half2_rn(v0, v1);
            }
        }

        // ---- grid barrier + next step's A prologue ----
        if (t < S_ - 1) {
            __syncthreads();
            if (tid == 0) {
                asm volatile("red.release.gpu.add.u32 [%0], %1;"
                             :: "l"(&g_bar), "r"(1u) : "memory");
                unsigned tgt = 128u * (unsigned)t;
                unsigned v;
                do {
                    asm volatile("ld.acquire.gpu.u32 %0, [%1];"
                                 : "=r"(v) : "l"(&g_bar) : "memory");
                } while (v < tgt);
            }
            __syncthreads();

            As = (const char*)Cg;
            LOAD_A(As, 0, 0);
            LOAD_A(As, 1, 1);
            LOAD_A(As, 2, 2);
        }
    }
#undef LOAD_A
#undef LOAD_AFRAGS
}

// ---------------------------------------------------------------------------
// Output: o = hT @ W_oh^T + b_oh ; softmax over O=10 (h fp16, in g_h1)
// ---------------------------------------------------------------------------
__global__ __launch_bounds__(256)
void output_softmax_kernel(const float* __restrict__ W_oh,
                           const float* __restrict__ b_oh,
                           float* __restrict__ out) {
    const int b = blockIdx.x;
    const int tid = threadIdx.x;
    const __half* hrow = g_h1 + (size_t)b * H_;

    float acc[O_];
#pragma unroll
    for (int j = 0; j < O_; j++) acc[j] = 0.f;

    for (int k = tid; k < H_; k += 256) {
        float hv = __half2float(hrow[k]);
#pragma unroll
        for (int j = 0; j < O_; j++) acc[j] += hv * W_oh[j * H_ + k];
    }
#pragma unroll
    for (int off = 16; off > 0; off >>= 1)
#pragma unroll
        for (int j = 0; j < O_; j++)
            acc[j] += __shfl_down_sync(0xffffffffu, acc[j], off);

    __shared__ float part[8][O_];
    if ((tid & 31) == 0) {
#pragma unroll
        for (int j = 0; j < O_; j++) part[tid >> 5][j] = acc[j];
    }
    __syncthreads();

    if (tid == 0) {
        float o[O_];
#pragma unroll
        for (int j = 0; j < O_; j++) {
            float s = b_oh[j];
#pragma unroll
            for (int w = 0; w < 8; w++) s += part[w][j];
            o[j] = s;
        }
        float m = o[0];
#pragma unroll
        for (int j = 1; j < O_; j++) m = fmaxf(m, o[j]);
        float s = 0.f;
#pragma unroll
        for (int j = 0; j < O_; j++) { o[j] = expf(o[j] - m); s += o[j]; }
        float inv = 1.f / s;
#pragma unroll
        for (int j = 0; j < O_; j++) out[b * O_ + j] = o[j] * inv;
    }
}

// ---------------------------------------------------------------------------
// Launch (graph-capturable; no allocs/syncs).
// Inputs: x, embed, W_hx, b_hx, W_hh, b_hh, W_oh, b_oh
// ---------------------------------------------------------------------------
#define STEP_SMEM (1024 + NB * TILE_BYTES)

extern "C" void kernel_launch(void* const* d_in, const int* in_sizes, int n_in,
                              void* d_out, int out_size) {
    const int*   x     = (const int*)  d_in[0];
    const float* embed = (const float*)d_in[1];
    const float* W_hx  = (const float*)d_in[2];
    const float* b_hx  = (const float*)d_in[3];
    const float* W_hh  = (const float*)d_in[4];
    const float* b_hh  = (const float*)d_in[5];
    const float* W_oh  = (const float*)d_in[6];
    const float* b_oh  = (const float*)d_in[7];
    float* out = (float*)d_out;

    cudaFuncSetAttribute(rnn_persist,
                         cudaFuncAttributeMaxDynamicSharedMemorySize, STEP_SMEM);

    precompute_T_kernel<<<dim3(H_ / 256, V_), 256>>>(embed, W_hx, b_hx);
    make_T2_kernel<<<(V_ * H_) / 256, 256>>>(b_hh);
    pack_W_kernel<<<(H_ * H_) / 256, 256>>>(W_hh);
    init_h_kernel<<<(B_ * H_) / 256, 256>>>(x);

    rnn_persist<<<dim3(H_ / BN, B_ / BM), 256, STEP_SMEM>>>(x);   // (16,8)=128 CTAs

    output_softmax_kernel<<<B_, 256>>>(W_oh, b_oh, out);
}

// round 13
// speedup vs baseline: 1.8541x; 1.1101x over previous
#include <cuda_runtime.h>
#include <cuda_fp16.h>
#include <math.h>
#include <stdint.h>

// Problem constants
#define B_   1024
#define S_   128
#define D_   256
#define H_   2048
#define O_   10
#define V_   10

// Step tiling
#define BM   128
#define BN   128
#define KT   64            // fp16 per K-tile => 128B/row (SW128 atom)
#define NKT  (H_ / KT)     // 32
#define NB   4             // 4-stage cp.async pipeline
#define TILE_BYTES 16384   // 128 rows x 128B
#define NTHR 512           // 16 warps, 4x4 warp grid, 32x32 warp tile

// Scratch
__device__ __half g_h0[B_ * H_];
__device__ __half g_h1[B_ * H_];
__device__ float  g_T [V_ * H_];    // W_hx @ embed[v] + b_hx   (for h0)
__device__ float  g_T2[V_ * H_];    // g_T + b_hh               (for steps)
__device__ __half g_Wh[H_ * H_];    // fp16 W_hh, row-major [h][k]
__device__ unsigned g_bar;          // grid barrier (cumulative)

// ---------------------------------------------------------------------------
// helpers
// ---------------------------------------------------------------------------
__device__ __forceinline__ uint32_t smem_u32(const void* p) {
    uint32_t a;
    asm("{ .reg .u64 t; cvta.to.shared.u64 t, %1; cvt.u32.u64 %0, t; }" : "=r"(a) : "l"(p));
    return a;
}
#define SWZ128(o) ((o) ^ (((o) >> 3) & 0x70))

#define CP_ASYNC16(dst, src) \
    asm volatile("cp.async.cg.shared.global [%0], [%1], 16;\n" :: "r"(dst), "l"(src))
#define CP_COMMIT() asm volatile("cp.async.commit_group;\n" ::: "memory")
#define CP_WAIT(n)  asm volatile("cp.async.wait_group %0;\n" :: "n"(n) : "memory")

#define LDSM4(R, A)                                                        \
    asm volatile("ldmatrix.sync.aligned.m8n8.x4.shared.b16 "               \
                 "{%0,%1,%2,%3}, [%4];"                                    \
                 : "=r"((R)[0]), "=r"((R)[1]), "=r"((R)[2]), "=r"((R)[3])  \
                 : "r"(A))

__device__ __forceinline__ void mma16816(float* d, const uint32_t* a,
                                         uint32_t b0, uint32_t b1) {
    asm volatile(
        "mma.sync.aligned.m16n8k16.row.col.f32.f16.f16.f32 "
        "{%0,%1,%2,%3}, {%4,%5,%6,%7}, {%8,%9}, {%0,%1,%2,%3};\n"
        : "+f"(d[0]), "+f"(d[1]), "+f"(d[2]), "+f"(d[3])
        : "r"(a[0]), "r"(a[1]), "r"(a[2]), "r"(a[3]), "r"(b0), "r"(b1));
}

// tanh(x) = 1 - 2/(e^{2x}+1) via MUFU ex2 + rcp; rel err ~1e-6.
__device__ __forceinline__ float fast_tanh(float x) {
    float e;
    asm("ex2.approx.f32 %0, %1;" : "=f"(e) : "f"(x * 2.8853900817779268f));
    float r;
    asm("rcp.approx.f32 %0, %1;" : "=f"(r) : "f"(e + 1.0f));
    return fmaf(-2.0f, r, 1.0f);
}

// ---------------------------------------------------------------------------
// Setup kernels
// ---------------------------------------------------------------------------
__global__ void precompute_T_kernel(const float* __restrict__ embed,
                                    const float* __restrict__ W_hx,
                                    const float* __restrict__ b_hx) {
    int h = blockIdx.x * blockDim.x + threadIdx.x;
    int v = blockIdx.y;
    if (h >= H_) return;
    const float4* wr = reinterpret_cast<const float4*>(W_hx + (size_t)h * D_);
    const float4* er = reinterpret_cast<const float4*>(embed + (size_t)v * D_);
    float s = 0.f;
#pragma unroll 8
    for (int i = 0; i < D_ / 4; i++) {
        float4 w = wr[i];
        float4 e = er[i];
        s += w.x * e.x + w.y * e.y + w.z * e.z + w.w * e.w;
    }
    g_T[v * H_ + h] = s + b_hx[h];
}

__global__ void make_T2_kernel(const float* __restrict__ b_hh) {
    int i = blockIdx.x * blockDim.x + threadIdx.x;
    g_T2[i] = g_T[i] + b_hh[i & (H_ - 1)];
}

__global__ void cvt_W_kernel(const float* __restrict__ W) {
    int i = blockIdx.x * blockDim.x + threadIdx.x;
    g_Wh[i] = __float2half(W[i]);
}

__global__ void init_h_kernel(const int* __restrict__ x) {
    int idx = blockIdx.x * blockDim.x + threadIdx.x;
    if (idx == 0) g_bar = 0u;
    int b = idx >> 11;
    int h = idx & (H_ - 1);
    int tok = x[b * S_];
    g_h0[idx] = __float2half(fast_tanh(g_T[tok * H_ + h]));
}

// ---------------------------------------------------------------------------
// Persistent recurrence kernel. Grid (16,8)=128 CTAs (one wave), 512 threads,
// 16 warps in 4x4 grid, warp tile 32x32. Per step: 128x128x2048 fp16 HMMA
// with 4-stage cp.async staging (SW128), fused epilogue, grid barrier.
// ---------------------------------------------------------------------------
__global__ __launch_bounds__(NTHR, 1)
void rnn_persist(const int* __restrict__ x) {
    extern __shared__ char dsm[];
    const uint32_t sraw = smem_u32(dsm);
    const uint32_t smA  = (sraw + 1023) & ~1023u;
    const uint32_t smB  = smA + NB * TILE_BYTES;

    const int tid  = threadIdx.x;
    const int warp = tid >> 5;
    const int lane = tid & 31;
    const int bm0  = blockIdx.y * BM;
    const int bn0  = blockIdx.x * BN;
    const int wm   = warp >> 2;      // 0..3  (M quarter: 32 rows)
    const int wn   = warp & 3;       // 0..3  (N quarter: 32 cols)

    // ---- loader mapping: 4 x cp.async(16B)/thread: 2 A rows + 2 B rows ----
    const int ch8 = tid & 7;         // 16B chunk within 128B row
    const int r0  = tid >> 3;        // 0..63
    size_t aoff[2];
    const char* gB[2];
    uint32_t offR[2];
#pragma unroll
    for (int j = 0; j < 2; j++) {
        int row = r0 + 64 * j;
        aoff[j] = (size_t)(bm0 + row) * (H_ * 2) + ch8 * 16;
        gB[j]   = (const char*)(g_Wh + (size_t)(bn0 + row) * H_) + ch8 * 16;
        offR[j] = SWZ128((uint32_t)(row * 128 + ch8 * 16));
    }

#define LOAD_TILE(ABASE, TT, BUF)                                     \
    do {                                                              \
        size_t _kb = (size_t)(TT) * 128;                              \
        uint32_t _da = smA + (BUF) * TILE_BYTES;                      \
        uint32_t _db = smB + (BUF) * TILE_BYTES;                      \
        CP_ASYNC16(_da + offR[0], (ABASE) + aoff[0] + _kb);           \
        CP_ASYNC16(_da + offR[1], (ABASE) + aoff[1] + _kb);           \
        CP_ASYNC16(_db + offR[0], gB[0] + _kb);                       \
        CP_ASYNC16(_db + offR[1], gB[1] + _kb);                       \
        CP_COMMIT();                                                  \
    } while (0)

    // ---- ldmatrix lane addresses (SW128) ----
    // A frags f=0,1: rows wm*32 + f*16 + (lane&7) + ((lane>>3)&1)*8, pA=lane>>4
    uint32_t rA128[2], rA7[2];
    const uint32_t pA = lane >> 4;
#pragma unroll
    for (int f = 0; f < 2; f++) {
        uint32_t r = wm * 32 + f * 16 + (lane & 7) + ((lane >> 3) & 1) * 8;
        rA128[f] = r * 128;
        rA7[f]   = r & 7;
    }
    // B frags q=0,1: rows wn*32 + q*16 + (lane&7) + ((lane>>4)&1)*8, pB=(lane>>3)&1
    uint32_t rB128[2], rB7[2];
    const uint32_t pB = (lane >> 3) & 1;
#pragma unroll
    for (int q = 0; q < 2; q++) {
        uint32_t r = wn * 32 + q * 16 + (lane & 7) + ((lane >> 4) & 1) * 8;
        rB128[q] = r * 128;
        rB7[q]   = r & 7;
    }

#define LOAD_FRAGS(DA, DB, SA, SB, S)                                            \
    do {                                                                         \
        _Pragma("unroll")                                                        \
        for (int _f = 0; _f < 2; _f++) {                                         \
            uint32_t _ad = (SA) + rA128[_f] + ((((2u*(S)) + pA) ^ rA7[_f]) << 4);\
            LDSM4((DA)[_f], _ad);                                                \
        }                                                                        \
        _Pragma("unroll")                                                        \
        for (int _q = 0; _q < 2; _q++) {                                         \
            uint32_t _ad = (SB) + rB128[_q] + ((((2u*(S)) + pB) ^ rB7[_q]) << 4);\
            LDSM4((DB)[_q], _ad);                                                \
        }                                                                        \
    } while (0)

    // epilogue constants
    const int erlo = bm0 + wm * 32 + (lane >> 2);    // + f*16
    const int ecol = bn0 + wn * 32 + (lane & 3) * 2; // + n*8

    // ---- prologue for step 1: stages 0..2 (A from g_h0) ----
    const char* As = (const char*)g_h0;
    LOAD_TILE(As, 0, 0);
    LOAD_TILE(As, 1, 1);
    LOAD_TILE(As, 2, 2);

    // ---- time loop ----
#pragma unroll 1
    for (int t = 1; t < S_; ++t) {
        const int par = (t - 1) & 1;
        __half* __restrict__ Cg = par ? g_h0 : g_h1;

        float acc[2][4][4];
#pragma unroll
        for (int f = 0; f < 2; f++)
#pragma unroll
            for (int n = 0; n < 4; n++)
#pragma unroll
                for (int k = 0; k < 4; k++) acc[f][n][k] = 0.f;

        uint32_t afr[2][2][4], bfr[2][2][4];

#pragma unroll 1
        for (int it = 0; it < NKT; ++it) {
            if (it < NKT - 2)       { CP_WAIT(2); }
            else if (it == NKT - 2) { CP_WAIT(1); }
            else                    { CP_WAIT(0); }
            __syncthreads();
            if (it + 3 < NKT) LOAD_TILE(As, it + 3, (it + 3) & 3);

            const uint32_t sa = smA + (it & 3) * TILE_BYTES;
            const uint32_t sb = smB + (it & 3) * TILE_BYTES;

            LOAD_FRAGS(afr[0], bfr[0], sa, sb, 0);
#pragma unroll
            for (int s = 0; s < 4; s++) {
                const int cur = s & 1;
                if (s < 3) LOAD_FRAGS(afr[cur ^ 1], bfr[cur ^ 1], sa, sb, s + 1);
#pragma unroll
                for (int f = 0; f < 2; f++)
#pragma unroll
                    for (int n = 0; n < 4; n++)
                        mma16816(acc[f][n], afr[cur][f],
                                 bfr[cur][n >> 1][(n & 1) * 2],
                                 bfr[cur][n >> 1][(n & 1) * 2 + 1]);
            }
        }

        // ---- fused epilogue: + T2[x[b,t]], tanh, fp16 store ----
#pragma unroll
        for (int f = 0; f < 2; f++) {
            int rlo = erlo + f * 16;
            int rhi = rlo + 8;
            const float* Tlo = g_T2 + x[rlo * S_ + t] * H_;
            const float* Thi = g_T2 + x[rhi * S_ + t] * H_;
#pragma unroll
            for (int n = 0; n < 4; n++) {
                int col = ecol + n * 8;
                float v0 = fast_tanh(acc[f][n][0] + Tlo[col]);
                float v1 = fast_tanh(acc[f][n][1] + Tlo[col + 1]);
                *(__half2*)(Cg + (size_t)rlo * H_ + col) = __floats2half2_rn(v0, v1);
                v0 = fast_tanh(acc[f][n][2] + Thi[col]);
                v1 = fast_tanh(acc[f][n][3] + Thi[col + 1]);
                *(__half2*)(Cg + (size_t)rhi * H_ + col) = __floats2half2_rn(v0, v1);
            }
        }

        // ---- grid barrier + next step's A prologue ----
        if (t < S_ - 1) {
            __syncthreads();
            if (tid == 0) {
                asm volatile("red.release.gpu.add.u32 [%0], %1;"
                             :: "l"(&g_bar), "r"(1u) : "memory");
                unsigned tgt = 128u * (unsigned)t;
                unsigned v;
                do {
                    asm volatile("ld.acquire.gpu.u32 %0, [%1];"
                                 : "=r"(v) : "l"(&g_bar) : "memory");
                } while (v < tgt);
            }
            __syncthreads();

            As = (const char*)Cg;
            LOAD_TILE(As, 0, 0);
            LOAD_TILE(As, 1, 1);
            LOAD_TILE(As, 2, 2);
        }
    }
#undef LOAD_TILE
#undef LOAD_FRAGS
}

// ---------------------------------------------------------------------------
// Output: o = hT @ W_oh^T + b_oh ; softmax over O=10 (h fp16, in g_h1)
// ---------------------------------------------------------------------------
__global__ __launch_bounds__(256)
void output_softmax_kernel(const float* __restrict__ W_oh,
                           const float* __restrict__ b_oh,
                           float* __restrict__ out) {
    const int b = blockIdx.x;
    const int tid = threadIdx.x;
    const __half* hrow = g_h1 + (size_t)b * H_;

    float acc[O_];
#pragma unroll
    for (int j = 0; j < O_; j++) acc[j] = 0.f;

    for (int k = tid; k < H_; k += 256) {
        float hv = __half2float(hrow[k]);
#pragma unroll
        for (int j = 0; j < O_; j++) acc[j] += hv * W_oh[j * H_ + k];
    }
#pragma unroll
    for (int off = 16; off > 0; off >>= 1)
#pragma unroll
        for (int j = 0; j < O_; j++)
            acc[j] += __shfl_down_sync(0xffffffffu, acc[j], off);

    __shared__ float part[8][O_];
    if ((tid & 31) == 0) {
#pragma unroll
        for (int j = 0; j < O_; j++) part[tid >> 5][j] = acc[j];
    }
    __syncthreads();

    if (tid == 0) {
        float o[O_];
#pragma unroll
        for (int j = 0; j < O_; j++) {
            float s = b_oh[j];
#pragma unroll
            for (int w = 0; w < 8; w++) s += part[w][j];
            o[j] = s;
        }
        float m = o[0];
#pragma unroll
        for (int j = 1; j < O_; j++) m = fmaxf(m, o[j]);
        float s = 0.f;
#pragma unroll
        for (int j = 0; j < O_; j++) { o[j] = expf(o[j] - m); s += o[j]; }
        float inv = 1.f / s;
#pragma unroll
        for (int j = 0; j < O_; j++) out[b * O_ + j] = o[j] * inv;
    }
}

// ---------------------------------------------------------------------------
// Launch (graph-capturable; no allocs/syncs).
// Inputs: x, embed, W_hx, b_hx, W_hh, b_hh, W_oh, b_oh
// ---------------------------------------------------------------------------
#define STEP_SMEM (1024 + 2 * NB * TILE_BYTES)

extern "C" void kernel_launch(void* const* d_in, const int* in_sizes, int n_in,
                              void* d_out, int out_size) {
    const int*   x     = (const int*)  d_in[0];
    const float* embed = (const float*)d_in[1];
    const float* W_hx  = (const float*)d_in[2];
    const float* b_hx  = (const float*)d_in[3];
    const float* W_hh  = (const float*)d_in[4];
    const float* b_hh  = (const float*)d_in[5];
    const float* W_oh  = (const float*)d_in[6];
    const float* b_oh  = (const float*)d_in[7];
    float* out = (float*)d_out;

    cudaFuncSetAttribute(rnn_persist,
                         cudaFuncAttributeMaxDynamicSharedMemorySize, STEP_SMEM);

    precompute_T_kernel<<<dim3(H_ / 256, V_), 256>>>(embed, W_hx, b_hx);
    make_T2_kernel<<<(V_ * H_) / 256, 256>>>(b_hh);
    cvt_W_kernel<<<(H_ * H_) / 256, 256>>>(W_hh);
    init_h_kernel<<<(B_ * H_) / 256, 256>>>(x);

    rnn_persist<<<dim3(H_ / BN, B_ / BM), NTHR, STEP_SMEM>>>(x);  // (16,8)=128 CTAs

    output_softmax_kernel<<<B_, 256>>>(W_oh, b_oh, out);
}